// round 12
// baseline (speedup 1.0000x reference)
#include <cuda_runtime.h>

// Bundle-adjustment reprojection residual.
//   d_in[0] observes  float32 [N_OBS, 2]
//   d_in[1] K         float32 [3, 3]
//   d_in[2] poses     float32 [N_CAM, 7]   (t[3], qv[3], qw)
//   d_in[3] points    float32 [N_PTS, 3]
//   d_in[4] cidx      int32   [N_OBS]
//   d_in[5] pidx      int32   [N_OBS]
// Output: float32 [N_OBS*2]  residual = proj - observe
//
// R11 strategy:
//  - prologue repacks points into float4 (one LDG.128 per gather)
//  - pose table in smem as two float4 arrays (64KB)
//  - 256-thread blocks, 2/SM -> 128-reg budget
//  - 8 obs per thread: ALL 8 point gathers + streams issued up front (MLP=8+)

#define THREADS 256
#define OBS_PER_THREAD 8   // 2 quads
#define N_PTS_MAX 500032

__device__ float4 g_points4[N_PTS_MAX];

// Each thread repacks 4 points: reads 3 float4 (12 floats), writes 4 float4.
__global__ __launch_bounds__(256) void repack_points_kernel(
    const float4* __restrict__ points4, const float* __restrict__ points,
    int n_quads, int n_pts)
{
    int i = blockIdx.x * blockDim.x + threadIdx.x;
    if (i < n_quads) {
        float4 v0 = __ldg(&points4[3 * i]);
        float4 v1 = __ldg(&points4[3 * i + 1]);
        float4 v2 = __ldg(&points4[3 * i + 2]);
        g_points4[4 * i + 0] = make_float4(v0.x, v0.y, v0.z, 0.0f);
        g_points4[4 * i + 1] = make_float4(v0.w, v1.x, v1.y, 0.0f);
        g_points4[4 * i + 2] = make_float4(v1.z, v1.w, v2.x, 0.0f);
        g_points4[4 * i + 3] = make_float4(v2.y, v2.z, v2.w, 0.0f);
    }
    int rem_base = n_quads * 4;
    int r = rem_base + i;
    if (blockIdx.x == 0 && r < n_pts) {
        const float* p = points + (size_t)r * 3;
        g_points4[r] = make_float4(__ldg(p), __ldg(p + 1), __ldg(p + 2), 0.0f);
    }
}

__global__ __launch_bounds__(THREADS, 2) void residual_kernel(
    const float4* __restrict__ obs4,
    const float* __restrict__ K,
    const float* __restrict__ poses,
    const int4* __restrict__ cidx4,
    const int4* __restrict__ pidx4,
    const int* __restrict__ cidx,
    const int* __restrict__ pidx,
    const float2* __restrict__ obs2,
    float4* __restrict__ out4,
    float2* __restrict__ out2,
    int n_obs, int n_cam)
{
    extern __shared__ float4 psm[];   // [n_cam] a-rows then [n_cam] b-rows
    float4* pa_t = psm;               // tx ty tz qx
    float4* pb_t = psm + n_cam;       // qy qz qw pad

    const int tid = threadIdx.x;

    // Stage poses: 7 floats/cam -> split float4 tables.
    {
        float* a_f = (float*)pa_t;
        float* b_f = (float*)pb_t;
        const int n_pose_f = n_cam * 7;
        for (int idx = tid; idx < n_pose_f; idx += THREADS) {
            int c = idx / 7;
            int k = idx - c * 7;
            float v = __ldg(&poses[idx]);
            if (k < 4) a_f[c * 4 + k] = v;
            else       b_f[c * 4 + (k - 4)] = v;
        }
    }
    __syncthreads();

    const float fx = __ldg(&K[0]);
    const float cxx = __ldg(&K[2]);
    const float fy = __ldg(&K[4]);
    const float cyy = __ldg(&K[5]);

    // Work unit: one "oct" = 2 consecutive quads = 8 obs per thread.
    const int n_octs = n_obs >> 3;             // full 8-obs groups
    const int gsz = gridDim.x * THREADS;

    for (int o = blockIdx.x * THREADS + tid; o < n_octs; o += gsz) {
        const int q0 = 2 * o;
        const int q1 = 2 * o + 1;

        // ---- issue ALL independent loads up front ----
        int4 cA = __ldg(&cidx4[q0]);
        int4 cB = __ldg(&cidx4[q1]);
        int4 pA = __ldg(&pidx4[q0]);
        int4 pB = __ldg(&pidx4[q1]);

        float4 ob[4];
        ob[0] = __ldg(&obs4[2 * q0]);
        ob[1] = __ldg(&obs4[2 * q0 + 1]);
        ob[2] = __ldg(&obs4[2 * q1]);
        ob[3] = __ldg(&obs4[2 * q1 + 1]);

        int pis[8] = {pA.x, pA.y, pA.z, pA.w, pB.x, pB.y, pB.z, pB.w};
        int cis[8] = {cA.x, cA.y, cA.z, cA.w, cB.x, cB.y, cB.z, cB.w};

        // 8 independent point gathers (LDG.128 each) — deep MLP batch
        float4 pt[8];
        #pragma unroll
        for (int j = 0; j < 8; j++)
            pt[j] = __ldg(&g_points4[pis[j]]);

        float obx[8] = {ob[0].x, ob[0].z, ob[1].x, ob[1].z,
                        ob[2].x, ob[2].z, ob[3].x, ob[3].z};
        float oby[8] = {ob[0].y, ob[0].w, ob[1].y, ob[1].w,
                        ob[2].y, ob[2].w, ob[3].y, ob[3].w};

        float res[16];

        #pragma unroll
        for (int j = 0; j < 8; j++) {
            float4 a = pa_t[cis[j]];
            float4 b = pb_t[cis[j]];
            float tx = a.x, ty = a.y, tz = a.z;
            float qx = a.w, qy = b.x, qz = b.y, qw = b.z;
            float X = pt[j].x, Y = pt[j].y, Z = pt[j].z;

            float uvx = qy * Z - qz * Y;
            float uvy = qz * X - qx * Z;
            float uvz = qx * Y - qy * X;
            float wx = fmaf(qw, X, uvx);
            float wy = fmaf(qw, Y, uvy);
            float wz = fmaf(qw, Z, uvz);
            float c2x = qy * wz - qz * wy;
            float c2y = qz * wx - qx * wz;
            float c2z = qx * wy - qy * wx;
            float Xc = fmaf(2.0f, c2x, X) + tx;
            float Yc = fmaf(2.0f, c2y, Y) + ty;
            float Zc = fmaf(2.0f, c2z, Z) + tz;

            float invz = __fdividef(1.0f, Zc);
            res[2 * j + 0] = fmaf(fx * Xc, invz, cxx) - obx[j];
            res[2 * j + 1] = fmaf(fy * Yc, invz, cyy) - oby[j];
        }

        out4[2 * q0]     = make_float4(res[0],  res[1],  res[2],  res[3]);
        out4[2 * q0 + 1] = make_float4(res[4],  res[5],  res[6],  res[7]);
        out4[2 * q1]     = make_float4(res[8],  res[9],  res[10], res[11]);
        out4[2 * q1 + 1] = make_float4(res[12], res[13], res[14], res[15]);
    }

    // ---- tail: n_obs % 8 leftovers (block 0 only; empty for N_OBS=5M) ----
    const int rem_base = n_octs << 3;
    if (blockIdx.x == 0) {
        for (int i = rem_base + tid; i < n_obs; i += THREADS) {
            int ci = __ldg(&cidx[i]);
            int pi = __ldg(&pidx[i]);
            float4 a = pa_t[ci];
            float4 b = pb_t[ci];
            float tx = a.x, ty = a.y, tz = a.z;
            float qx = a.w, qy = b.x, qz = b.y, qw = b.z;
            float4 p = __ldg(&g_points4[pi]);
            float X = p.x, Y = p.y, Z = p.z;

            float uvx = qy * Z - qz * Y;
            float uvy = qz * X - qx * Z;
            float uvz = qx * Y - qy * X;
            float wx = fmaf(qw, X, uvx);
            float wy = fmaf(qw, Y, uvy);
            float wz = fmaf(qw, Z, uvz);
            float c2x = qy * wz - qz * wy;
            float c2y = qz * wx - qx * wz;
            float c2z = qx * wy - qy * wx;
            float Xc = fmaf(2.0f, c2x, X) + tx;
            float Yc = fmaf(2.0f, c2y, Y) + ty;
            float Zc = fmaf(2.0f, c2z, Z) + tz;
            float invz = __fdividef(1.0f, Zc);
            float2 obv = __ldg(&obs2[i]);
            float2 r;
            r.x = fmaf(fx * Xc, invz, cxx) - obv.x;
            r.y = fmaf(fy * Yc, invz, cyy) - obv.y;
            out2[i] = r;
        }
    }
}

extern "C" void kernel_launch(void* const* d_in, const int* in_sizes, int n_in,
                              void* d_out, int out_size) {
    const float* observes = (const float*)d_in[0];
    const float* K        = (const float*)d_in[1];
    const float* poses    = (const float*)d_in[2];
    const float* points   = (const float*)d_in[3];
    const int* cidx       = (const int*)d_in[4];
    const int* pidx       = (const int*)d_in[5];

    int n_obs = in_sizes[0] / 2;
    int n_cam = in_sizes[2] / 7;
    int n_pts = in_sizes[3] / 3;
    if (n_pts > N_PTS_MAX) n_pts = N_PTS_MAX;

    int smem = n_cam * 2 * sizeof(float4);  // 64000 B for n_cam=2000

    cudaFuncSetAttribute(residual_kernel,
                         cudaFuncAttributeMaxDynamicSharedMemorySize, smem);

    int pq = n_pts / 4;
    int pblocks = (pq + 255) / 256;
    if (pblocks < 1) pblocks = 1;
    repack_points_kernel<<<pblocks, 256>>>((const float4*)points, points, pq, n_pts);

    int blocks = 148 * 2;  // 2 blocks/SM, 128-reg budget per thread
    residual_kernel<<<blocks, THREADS, smem>>>(
        (const float4*)observes, K, poses,
        (const int4*)cidx, (const int4*)pidx,
        cidx, pidx, (const float2*)observes,
        (float4*)d_out, (float2*)d_out,
        n_obs, n_cam);
}

// round 13
// speedup vs baseline: 1.1513x; 1.1513x over previous
#include <cuda_runtime.h>

// Bundle-adjustment reprojection residual — fused single kernel.
//   d_in[0] observes  float32 [N_OBS, 2]
//   d_in[1] K         float32 [3, 3]
//   d_in[2] poses     float32 [N_CAM, 7]   (t[3], qv[3], qw)
//   d_in[3] points    float32 [N_PTS, 3]
//   d_in[4] cidx      int32   [N_OBS]
//   d_in[5] pidx      int32   [N_OBS]
// Output: float32 [N_OBS*2]  residual = proj - observe
//
// R13: single persistent kernel (grid=296=2/SM, all blocks co-resident):
//   phase 1: stage poses into smem split-float4 tables (64KB)
//            + repack points [N,3]->float4 table (coalesced slice per block)
//   software grid barrier (atomic counter, reset via cudaMemsetAsync each launch)
//   phase 2: batch-4 main loop (one LDG.128 per point gather, 2 LDS.128 per pose)

#define THREADS 512
#define NBLOCKS 296          // 2 per SM on 148 SMs; <= resident capacity
#define N_PTS_MAX 500032

__device__ float4 g_points4[N_PTS_MAX];
__device__ unsigned int g_bar;

__global__ __launch_bounds__(THREADS, 2) void residual_fused_kernel(
    const float4* __restrict__ obs4,
    const float* __restrict__ K,
    const float* __restrict__ poses,
    const float4* __restrict__ points4,
    const float* __restrict__ points,
    const int4* __restrict__ cidx4,
    const int4* __restrict__ pidx4,
    float4* __restrict__ out4,
    int n_obs, int n_cam, int n_pts)
{
    extern __shared__ float4 psm[];   // [n_cam] a-rows then [n_cam] b-rows
    float4* pa_t = psm;               // tx ty tz qx
    float4* pb_t = psm + n_cam;       // qy qz qw pad

    const int tid = threadIdx.x;
    const int g = blockIdx.x * THREADS + tid;

    // ---------------- phase 1a: stage poses into smem ----------------
    {
        float* a_f = (float*)pa_t;
        float* b_f = (float*)pb_t;
        const int n_pose_f = n_cam * 7;
        for (int idx = tid; idx < n_pose_f; idx += THREADS) {
            int c = idx / 7;
            int k = idx - c * 7;
            float v = __ldg(&poses[idx]);
            if (k < 4) a_f[c * 4 + k] = v;
            else       b_f[c * 4 + (k - 4)] = v;
        }
    }

    // ---------------- phase 1b: repack points slice ----------------
    {
        const int pq = n_pts >> 2;  // quads of 4 points (12 floats = 3 float4)
        const int gsz = NBLOCKS * THREADS;
        for (int i = g; i < pq; i += gsz) {
            float4 v0 = __ldg(&points4[3 * i]);
            float4 v1 = __ldg(&points4[3 * i + 1]);
            float4 v2 = __ldg(&points4[3 * i + 2]);
            g_points4[4 * i + 0] = make_float4(v0.x, v0.y, v0.z, 0.0f);
            g_points4[4 * i + 1] = make_float4(v0.w, v1.x, v1.y, 0.0f);
            g_points4[4 * i + 2] = make_float4(v1.z, v1.w, v2.x, 0.0f);
            g_points4[4 * i + 3] = make_float4(v2.y, v2.z, v2.w, 0.0f);
        }
        // tail points (n_pts % 4): scalar loads, done by first few threads
        int r = (pq << 2) + g;
        if (r < n_pts) {
            const float* p = points + (size_t)r * 3;
            g_points4[r] = make_float4(__ldg(p), __ldg(p + 1), __ldg(p + 2), 0.0f);
        }
    }

    // ---------------- grid barrier (all blocks co-resident) ----------------
    __threadfence();
    __syncthreads();
    if (tid == 0) {
        atomicAdd(&g_bar, 1u);
        unsigned v;
        do {
            asm volatile("ld.global.acquire.gpu.u32 %0, [%1];"
                         : "=r"(v) : "l"(&g_bar));
            if (v >= (unsigned)gridDim.x) break;
            __nanosleep(64);
        } while (true);
    }
    __syncthreads();

    // ---------------- phase 2: main loop, 4 obs per thread ----------------
    const float fx = __ldg(&K[0]);
    const float cxx = __ldg(&K[2]);
    const float fy = __ldg(&K[4]);
    const float cyy = __ldg(&K[5]);

    const int n_quads = n_obs >> 2;
    const int gsz = NBLOCKS * THREADS;

    for (int q = g; q < n_quads; q += gsz) {
        int4 c4 = __ldg(&cidx4[q]);
        int4 p4 = __ldg(&pidx4[q]);

        float4 ob0 = __ldg(&obs4[2 * q]);
        float4 ob1 = __ldg(&obs4[2 * q + 1]);

        int pis[4] = {p4.x, p4.y, p4.z, p4.w};
        int cis[4] = {c4.x, c4.y, c4.z, c4.w};

        // one LDG.128 per point, all 4 issued up front
        float4 pt[4];
        #pragma unroll
        for (int j = 0; j < 4; j++)
            pt[j] = __ldg(&g_points4[pis[j]]);

        float res[8];
        float obx[4] = {ob0.x, ob0.z, ob1.x, ob1.z};
        float oby[4] = {ob0.y, ob0.w, ob1.y, ob1.w};

        #pragma unroll
        for (int j = 0; j < 4; j++) {
            float4 a = pa_t[cis[j]];
            float4 b = pb_t[cis[j]];
            float tx = a.x, ty = a.y, tz = a.z;
            float qx = a.w, qy = b.x, qz = b.y, qw = b.z;
            float X = pt[j].x, Y = pt[j].y, Z = pt[j].z;

            float uvx = qy * Z - qz * Y;
            float uvy = qz * X - qx * Z;
            float uvz = qx * Y - qy * X;
            float wx = fmaf(qw, X, uvx);
            float wy = fmaf(qw, Y, uvy);
            float wz = fmaf(qw, Z, uvz);
            float c2x = qy * wz - qz * wy;
            float c2y = qz * wx - qx * wz;
            float c2z = qx * wy - qy * wx;
            float Xc = fmaf(2.0f, c2x, X) + tx;
            float Yc = fmaf(2.0f, c2y, Y) + ty;
            float Zc = fmaf(2.0f, c2z, Z) + tz;

            float invz = __fdividef(1.0f, Zc);
            res[2 * j + 0] = fmaf(fx * Xc, invz, cxx) - obx[j];
            res[2 * j + 1] = fmaf(fy * Yc, invz, cyy) - oby[j];
        }

        out4[2 * q]     = make_float4(res[0], res[1], res[2], res[3]);
        out4[2 * q + 1] = make_float4(res[4], res[5], res[6], res[7]);
    }

    // ---- tail: n_obs % 4 leftovers (block 0; empty for N_OBS=5M) ----
    const int rem_base = n_quads << 2;
    if (blockIdx.x == 0) {
        const int* cidx = (const int*)cidx4;
        const int* pidx = (const int*)pidx4;
        const float2* obs2 = (const float2*)obs4;
        float2* out2 = (float2*)out4;
        for (int i = rem_base + tid; i < n_obs; i += THREADS) {
            int ci = __ldg(&cidx[i]);
            int pi = __ldg(&pidx[i]);
            float4 a = pa_t[ci];
            float4 b = pb_t[ci];
            float tx = a.x, ty = a.y, tz = a.z;
            float qx = a.w, qy = b.x, qz = b.y, qw = b.z;
            float4 p = __ldg(&g_points4[pi]);
            float X = p.x, Y = p.y, Z = p.z;

            float uvx = qy * Z - qz * Y;
            float uvy = qz * X - qx * Z;
            float uvz = qx * Y - qy * X;
            float wx = fmaf(qw, X, uvx);
            float wy = fmaf(qw, Y, uvy);
            float wz = fmaf(qw, Z, uvz);
            float c2x = qy * wz - qz * wy;
            float c2y = qz * wx - qx * wz;
            float c2z = qx * wy - qy * wx;
            float Xc = fmaf(2.0f, c2x, X) + tx;
            float Yc = fmaf(2.0f, c2y, Y) + ty;
            float Zc = fmaf(2.0f, c2z, Z) + tz;
            float invz = __fdividef(1.0f, Zc);
            float2 ob = __ldg(&obs2[i]);
            float2 r;
            r.x = fmaf(fx * Xc, invz, cxx) - ob.x;
            r.y = fmaf(fy * Yc, invz, cyy) - ob.y;
            out2[i] = r;
        }
    }
}

extern "C" void kernel_launch(void* const* d_in, const int* in_sizes, int n_in,
                              void* d_out, int out_size) {
    const float* observes = (const float*)d_in[0];
    const float* K        = (const float*)d_in[1];
    const float* poses    = (const float*)d_in[2];
    const float* points   = (const float*)d_in[3];
    const int* cidx       = (const int*)d_in[4];
    const int* pidx       = (const int*)d_in[5];

    int n_obs = in_sizes[0] / 2;
    int n_cam = in_sizes[2] / 7;
    int n_pts = in_sizes[3] / 3;
    if (n_pts > N_PTS_MAX) n_pts = N_PTS_MAX;

    int smem = n_cam * 2 * sizeof(float4);  // 64000 B for n_cam=2000

    cudaFuncSetAttribute(residual_fused_kernel,
                         cudaFuncAttributeMaxDynamicSharedMemorySize, smem);

    // Reset the grid-barrier counter (graph-capturable async memset).
    void* bar_ptr = nullptr;
    cudaGetSymbolAddress(&bar_ptr, g_bar);
    cudaMemsetAsync(bar_ptr, 0, sizeof(unsigned int));

    residual_fused_kernel<<<NBLOCKS, THREADS, smem>>>(
        (const float4*)observes, K, poses,
        (const float4*)points, points,
        (const int4*)cidx, (const int4*)pidx,
        (float4*)d_out,
        n_obs, n_cam, n_pts);
}

// round 14
// speedup vs baseline: 1.2113x; 1.0522x over previous
#include <cuda_runtime.h>

// Bundle-adjustment reprojection residual — fused single persistent kernel.
//   d_in[0] observes  float32 [N_OBS, 2]
//   d_in[1] K         float32 [3, 3]
//   d_in[2] poses     float32 [N_CAM, 7]   (t[3], qv[3], qw)
//   d_in[3] points    float32 [N_PTS, 3]
//   d_in[4] cidx      int32   [N_OBS]
//   d_in[5] pidx      int32   [N_OBS]
// Output: float32 [N_OBS*2]  residual = proj - observe
//
// R14:
//  - single fused kernel: pose->smem staging + point repack + grid barrier + main loop
//  - TICKET barrier: monotonically increasing counter, no per-launch reset
//    (removes the cudaMemsetAsync graph node)
//  - grid sized from multiProcessorCount (GB300 = 152 SMs) x 2 blocks/SM
//  - batch-4 main loop: one LDG.128 per point gather, 2 LDS.128 per pose

#define THREADS 512
#define N_PTS_MAX 500032

__device__ float4 g_points4[N_PTS_MAX];
__device__ unsigned int g_ticket;   // zero-initialized at module load; never reset

__global__ __launch_bounds__(THREADS, 2) void residual_fused_kernel(
    const float4* __restrict__ obs4,
    const float* __restrict__ K,
    const float* __restrict__ poses,
    const float4* __restrict__ points4,
    const float* __restrict__ points,
    const int4* __restrict__ cidx4,
    const int4* __restrict__ pidx4,
    float4* __restrict__ out4,
    int n_obs, int n_cam, int n_pts)
{
    extern __shared__ float4 psm[];   // [n_cam] a-rows then [n_cam] b-rows
    float4* pa_t = psm;               // tx ty tz qx
    float4* pb_t = psm + n_cam;       // qy qz qw pad

    const int tid = threadIdx.x;
    const int nblocks = gridDim.x;
    const int g = blockIdx.x * THREADS + tid;
    const int gsz = nblocks * THREADS;

    // ---------------- phase 1a: stage poses into smem ----------------
    {
        float* a_f = (float*)pa_t;
        float* b_f = (float*)pb_t;
        const int n_pose_f = n_cam * 7;
        for (int idx = tid; idx < n_pose_f; idx += THREADS) {
            int c = idx / 7;
            int k = idx - c * 7;
            float v = __ldg(&poses[idx]);
            if (k < 4) a_f[c * 4 + k] = v;
            else       b_f[c * 4 + (k - 4)] = v;
        }
    }

    // ---------------- phase 1b: repack points slice ----------------
    {
        const int pq = n_pts >> 2;  // groups of 4 points (12 floats = 3 float4)
        for (int i = g; i < pq; i += gsz) {
            float4 v0 = __ldg(&points4[3 * i]);
            float4 v1 = __ldg(&points4[3 * i + 1]);
            float4 v2 = __ldg(&points4[3 * i + 2]);
            g_points4[4 * i + 0] = make_float4(v0.x, v0.y, v0.z, 0.0f);
            g_points4[4 * i + 1] = make_float4(v0.w, v1.x, v1.y, 0.0f);
            g_points4[4 * i + 2] = make_float4(v1.z, v1.w, v2.x, 0.0f);
            g_points4[4 * i + 3] = make_float4(v2.y, v2.z, v2.w, 0.0f);
        }
        int r = (pq << 2) + g;
        if (r < n_pts) {
            const float* p = points + (size_t)r * 3;
            g_points4[r] = make_float4(__ldg(p), __ldg(p + 1), __ldg(p + 2), 0.0f);
        }
    }

    // ------------- ticket grid barrier (no reset across launches) -------------
    __threadfence();
    __syncthreads();
    if (tid == 0) {
        unsigned t = atomicAdd(&g_ticket, 1u);
        unsigned target = (t / (unsigned)nblocks + 1u) * (unsigned)nblocks;
        unsigned v;
        do {
            asm volatile("ld.global.acquire.gpu.u32 %0, [%1];"
                         : "=r"(v) : "l"(&g_ticket));
            if (v >= target) break;
            __nanosleep(64);
        } while (true);
    }
    __syncthreads();

    // ---------------- phase 2: main loop, 4 obs per thread ----------------
    const float fx = __ldg(&K[0]);
    const float cxx = __ldg(&K[2]);
    const float fy = __ldg(&K[4]);
    const float cyy = __ldg(&K[5]);

    const int n_quads = n_obs >> 2;

    for (int q = g; q < n_quads; q += gsz) {
        int4 c4 = __ldg(&cidx4[q]);
        int4 p4 = __ldg(&pidx4[q]);

        float4 ob0 = __ldg(&obs4[2 * q]);
        float4 ob1 = __ldg(&obs4[2 * q + 1]);

        int pis[4] = {p4.x, p4.y, p4.z, p4.w};
        int cis[4] = {c4.x, c4.y, c4.z, c4.w};

        // one LDG.128 per point, all 4 issued up front
        float4 pt[4];
        #pragma unroll
        for (int j = 0; j < 4; j++)
            pt[j] = __ldg(&g_points4[pis[j]]);

        // batch all pose LDS.128 issues before compute
        float4 pa[4], pb[4];
        #pragma unroll
        for (int j = 0; j < 4; j++) {
            pa[j] = pa_t[cis[j]];
            pb[j] = pb_t[cis[j]];
        }

        float res[8];
        float obx[4] = {ob0.x, ob0.z, ob1.x, ob1.z};
        float oby[4] = {ob0.y, ob0.w, ob1.y, ob1.w};

        #pragma unroll
        for (int j = 0; j < 4; j++) {
            float tx = pa[j].x, ty = pa[j].y, tz = pa[j].z;
            float qx = pa[j].w, qy = pb[j].x, qz = pb[j].y, qw = pb[j].z;
            float X = pt[j].x, Y = pt[j].y, Z = pt[j].z;

            float uvx = qy * Z - qz * Y;
            float uvy = qz * X - qx * Z;
            float uvz = qx * Y - qy * X;
            float wx = fmaf(qw, X, uvx);
            float wy = fmaf(qw, Y, uvy);
            float wz = fmaf(qw, Z, uvz);
            float c2x = qy * wz - qz * wy;
            float c2y = qz * wx - qx * wz;
            float c2z = qx * wy - qy * wx;
            float Xc = fmaf(2.0f, c2x, X) + tx;
            float Yc = fmaf(2.0f, c2y, Y) + ty;
            float Zc = fmaf(2.0f, c2z, Z) + tz;

            float invz = __fdividef(1.0f, Zc);
            res[2 * j + 0] = fmaf(fx * Xc, invz, cxx) - obx[j];
            res[2 * j + 1] = fmaf(fy * Yc, invz, cyy) - oby[j];
        }

        out4[2 * q]     = make_float4(res[0], res[1], res[2], res[3]);
        out4[2 * q + 1] = make_float4(res[4], res[5], res[6], res[7]);
    }

    // ---- tail: n_obs % 4 leftovers (block 0; empty for N_OBS=5M) ----
    const int rem_base = n_quads << 2;
    if (blockIdx.x == 0) {
        const int* cidx = (const int*)cidx4;
        const int* pidx = (const int*)pidx4;
        const float2* obs2 = (const float2*)obs4;
        float2* out2 = (float2*)out4;
        for (int i = rem_base + tid; i < n_obs; i += THREADS) {
            int ci = __ldg(&cidx[i]);
            int pi = __ldg(&pidx[i]);
            float4 a = pa_t[ci];
            float4 b = pb_t[ci];
            float tx = a.x, ty = a.y, tz = a.z;
            float qx = a.w, qy = b.x, qz = b.y, qw = b.z;
            float4 p = __ldg(&g_points4[pi]);
            float X = p.x, Y = p.y, Z = p.z;

            float uvx = qy * Z - qz * Y;
            float uvy = qz * X - qx * Z;
            float uvz = qx * Y - qy * X;
            float wx = fmaf(qw, X, uvx);
            float wy = fmaf(qw, Y, uvy);
            float wz = fmaf(qw, Z, uvz);
            float c2x = qy * wz - qz * wy;
            float c2y = qz * wx - qx * wz;
            float c2z = qx * wy - qy * wx;
            float Xc = fmaf(2.0f, c2x, X) + tx;
            float Yc = fmaf(2.0f, c2y, Y) + ty;
            float Zc = fmaf(2.0f, c2z, Z) + tz;
            float invz = __fdividef(1.0f, Zc);
            float2 ob = __ldg(&obs2[i]);
            float2 r;
            r.x = fmaf(fx * Xc, invz, cxx) - ob.x;
            r.y = fmaf(fy * Yc, invz, cyy) - ob.y;
            out2[i] = r;
        }
    }
}

extern "C" void kernel_launch(void* const* d_in, const int* in_sizes, int n_in,
                              void* d_out, int out_size) {
    const float* observes = (const float*)d_in[0];
    const float* K        = (const float*)d_in[1];
    const float* poses    = (const float*)d_in[2];
    const float* points   = (const float*)d_in[3];
    const int* cidx       = (const int*)d_in[4];
    const int* pidx       = (const int*)d_in[5];

    int n_obs = in_sizes[0] / 2;
    int n_cam = in_sizes[2] / 7;
    int n_pts = in_sizes[3] / 3;
    if (n_pts > N_PTS_MAX) n_pts = N_PTS_MAX;

    int smem = n_cam * 2 * sizeof(float4);  // 64000 B for n_cam=2000

    cudaFuncSetAttribute(residual_fused_kernel,
                         cudaFuncAttributeMaxDynamicSharedMemorySize, smem);

    // Grid = 2 blocks per actual SM (152 on GB300, 148 on B300).
    // Host-side query runs once at capture; co-residency (barrier safety)
    // holds because launch bounds guarantee 2 blocks/SM fit.
    int num_sm = 148;
    int dev = 0;
    cudaGetDevice(&dev);
    cudaDeviceGetAttribute(&num_sm, cudaDevAttrMultiProcessorCount, dev);
    int nblocks = 2 * num_sm;

    residual_fused_kernel<<<nblocks, THREADS, smem>>>(
        (const float4*)observes, K, poses,
        (const float4*)points, points,
        (const int4*)cidx, (const int4*)pidx,
        (float4*)d_out,
        n_obs, n_cam, n_pts);
}